// round 15
// baseline (speedup 1.0000x reference)
#include <cuda_runtime.h>
#include <cuda_fp16.h>
#include <cstdint>

#define B_  8
#define C_  64
#define HW_ 4096

// ---------------- scratch globals (no allocation) ----------------
__device__ __half g_q[(size_t)B_*HW_*C_];   // [b][n][c]  (scaled by log2e/8)
__device__ __half g_k[(size_t)B_*HW_*C_];   // [b][n][c]
__device__ __half g_v[(size_t)B_*HW_*C_];   // [b][n][c]

__device__ __forceinline__ uint32_t smem_u32(const void* p) {
    uint32_t a;
    asm("{ .reg .u64 t; cvta.to.shared.u64 t, %1; cvt.u32.u64 %0, t; }" : "=r"(a) : "l"(p));
    return a;
}

#define MMA16816(c, a, b0, b1)                                                  \
    asm volatile("mma.sync.aligned.m16n8k16.row.col.f32.f16.f16.f32 "           \
        "{%0,%1,%2,%3}, {%4,%5,%6,%7}, {%8,%9}, {%0,%1,%2,%3};"                 \
        : "+f"((c)[0]), "+f"((c)[1]), "+f"((c)[2]), "+f"((c)[3])                \
        : "r"((a)[0]), "r"((a)[1]), "r"((a)[2]), "r"((a)[3]), "r"(b0), "r"(b1))

#define LDSM4(r, a)                                                             \
    asm volatile("ldmatrix.sync.aligned.m8n8.x4.shared.b16 {%0,%1,%2,%3}, [%4];"\
        : "=r"((r)[0]), "=r"((r)[1]), "=r"((r)[2]), "=r"((r)[3]) : "r"(a))

#define LDSM4T(r, a)                                                            \
    asm volatile("ldmatrix.sync.aligned.m8n8.x4.trans.shared.b16 {%0,%1,%2,%3}, [%4];"\
        : "=r"((r)[0]), "=r"((r)[1]), "=r"((r)[2]), "=r"((r)[3]) : "r"(a))

#define CP16(dst, src) asm volatile("cp.async.cg.shared.global [%0], [%1], 16;" :: "r"(dst), "l"(src))
#define CP_COMMIT()    asm volatile("cp.async.commit_group;" ::: "memory")
#define CP_WAIT1()     asm volatile("cp.async.wait_group 1;" ::: "memory")
#define CP_WAIT0()     asm volatile("cp.async.wait_group 0;" ::: "memory")

// hardware exp2 (MUFU.EX2 f32)
__device__ __forceinline__ float fexp2(float x) {
    float y;
    asm("ex2.approx.f32 %0, %1;" : "=f"(y) : "f"(x));
    return y;
}

#define PITCH 144   // bytes per 64-half row (8 halves padding)

// ---------------------------------------------------------------------------
// QKV projection via HMMA. xs staging rebuilt: coalesced row-gather + 16B
// conflict-free stores (old version had 16-way bank conflicts on 2B stores).
// ---------------------------------------------------------------------------
__global__ __launch_bounds__(256) void qkv_kernel(
    const float* __restrict__ x,
    const float* __restrict__ wq, const float* __restrict__ bq,
    const float* __restrict__ wk, const float* __restrict__ bk,
    const float* __restrict__ wv, const float* __restrict__ bv)
{
    __shared__ __align__(16) char xs[128*PITCH];
    __shared__ __align__(16) char ws[3*64*PITCH];
    __shared__ float bsh[3*64];

    int tid = threadIdx.x, wid = tid >> 5, lane = tid & 31;
    int b  = blockIdx.x >> 5;
    int n0 = (blockIdx.x & 31) << 7;
    const float* xb = x + (size_t)b*C_*HW_;

    // x tile: thread gathers 8 channels of one token (each read coalesced
    // across lanes: row fast), packs to 8 halves, one 16B store (no conflicts)
    #pragma unroll
    for (int k = 0; k < 4; k++) {
        int e = tid + 256*k;              // 1024 tasks: 128 rows x 8 chunks
        int row = e & 127;
        int ch  = (e >> 7) & 7;
        const float* src = xb + (size_t)(ch*8)*HW_ + n0 + row;
        __half h[8];
        #pragma unroll
        for (int i = 0; i < 8; i++) h[i] = __float2half_rn(src[(size_t)i*HW_]);
        *(uint4*)(xs + row*PITCH + ch*16) = *(uint4*)h;
    }
    const float* wptr[3] = {wq, wk, wv};
    #pragma unroll
    for (int m = 0; m < 3; m++) {
        char* wsm = ws + m*64*PITCH;
        #pragma unroll
        for (int k = 0; k < 4; k++) {
            int e = tid + 256*k;
            int d = e >> 4, c4 = (e & 15) << 2;
            float4 v = *(const float4*)(wptr[m] + (size_t)d*C_ + c4);
            __half2 h01 = __floats2half2_rn(v.x, v.y);
            __half2 h23 = __floats2half2_rn(v.z, v.w);
            *(__half2*)(wsm + d*PITCH + c4*2)     = h01;
            *(__half2*)(wsm + d*PITCH + c4*2 + 4) = h23;
        }
    }
    if (tid < 192) {
        bsh[tid] = (tid < 64) ? bq[tid] : (tid < 128) ? bk[tid - 64] : bv[tid - 128];
    }
    __syncthreads();

    const uint32_t sxs = smem_u32(xs);
    const uint32_t sws = smem_u32(ws);

    uint32_t af[4][4];
    {
        int r  = 16*wid + (lane & 15);
        int cg = (lane >> 4) & 1;
        #pragma unroll
        for (int ks = 0; ks < 4; ks++)
            LDSM4(af[ks], sxs + r*PITCH + (ks*16 + cg*8)*2);
    }

    const uint32_t blane = ((lane & 7) + ((lane >> 4) & 1)*8)*PITCH + ((lane >> 3) & 1)*16;
    __half* outp[3] = {g_q + (size_t)b*HW_*C_, g_k + (size_t)b*HW_*C_, g_v + (size_t)b*HW_*C_};
    const float scl[3] = {0.18033688011112043f, 1.0f, 1.0f};   // log2(e)/8 on Q

    int r = lane >> 2, c0 = 2*(lane & 3);
    #pragma unroll
    for (int m = 0; m < 3; m++) {
        float acc[8][4];
        #pragma unroll
        for (int j = 0; j < 8; j++)
            #pragma unroll
            for (int c = 0; c < 4; c++) acc[j][c] = 0.f;

        const uint32_t wb = sws + m*64*PITCH + blane;
        #pragma unroll
        for (int ks = 0; ks < 4; ks++) {
            uint32_t f0[4], f1[4], f2[4], f3[4];
            LDSM4(f0, wb + 0*(16*PITCH) + ks*32);
            LDSM4(f1, wb + 1*(16*PITCH) + ks*32);
            LDSM4(f2, wb + 2*(16*PITCH) + ks*32);
            LDSM4(f3, wb + 3*(16*PITCH) + ks*32);
            MMA16816(acc[0], af[ks], f0[0], f0[1]);
            MMA16816(acc[1], af[ks], f0[2], f0[3]);
            MMA16816(acc[2], af[ks], f1[0], f1[1]);
            MMA16816(acc[3], af[ks], f1[2], f1[3]);
            MMA16816(acc[4], af[ks], f2[0], f2[1]);
            MMA16816(acc[5], af[ks], f2[2], f2[3]);
            MMA16816(acc[6], af[ks], f3[0], f3[1]);
            MMA16816(acc[7], af[ks], f3[2], f3[3]);
        }

        float sc = scl[m];
        __half* og = outp[m] + (size_t)(n0 + 16*wid + r)*C_;
        #pragma unroll
        for (int j = 0; j < 8; j++) {
            float bz0 = bsh[m*64 + 8*j + c0], bz1 = bsh[m*64 + 8*j + c0 + 1];
            __half2 lo = __floats2half2_rn((acc[j][0] + bz0)*sc, (acc[j][1] + bz1)*sc);
            __half2 hi = __floats2half2_rn((acc[j][2] + bz0)*sc, (acc[j][3] + bz1)*sc);
            *(__half2*)(og + 8*j + c0)        = lo;
            *(__half2*)(og + 8*C_ + 8*j + c0) = hi;
        }
    }
}

// ---------------------------------------------------------------------------
// Flash attention with CROSS-ITERATION pipeline: softmax(t) [MUFU] overlaps
// S(t+1) [tensor] within each warp (no data dependence). 4-stage cp.async
// K|V ring, issue 3 ahead, wait-leaving-1: tiles <= t+1 visible at iter t.
// Q fragments reloaded from persistent smem region (register diet).
// Epilogue: normalize + mix GEMM + ReLU + 2x2 avg pool.
// ---------------------------------------------------------------------------
#define SM_RING 18432                       // Q region [0,18432), ring after
#define STAGEB  18432                       // K 9216 + V 9216 per stage
#define ATTN_SMEM (18432 + 4*18432)         // 92160

__device__ __forceinline__ void load_tile_async(
    uint32_t sb, int st, const __half* kg, const __half* vg, int kn0, int tid)
{
    uint32_t kd = sb + SM_RING + st*STAGEB;
    const char* ksrc = (const char*)(kg + (size_t)kn0*C_);
    const char* vsrc = (const char*)(vg + (size_t)kn0*C_);
    #pragma unroll
    for (int k = 0; k < 2; k++) {
        int e = tid + 256*k;
        uint32_t doff = (e >> 3)*PITCH + (e & 7)*16;
        CP16(kd + doff,        ksrc + e*16);
        CP16(kd + 9216 + doff, vsrc + e*16);
    }
}

// one pipelined iteration: softmax+O on scur (tile t), S(t+1) into snxt
__device__ __forceinline__ void attn_iter(
    int t, uint32_t sb, const __half* kg, const __half* vg, int tid,
    uint32_t qbase, uint32_t klane, uint32_t vlane,
    float (&scur)[8][4], float (&snxt)[8][4],
    float (&oacc)[8][4], float& l0, float& l1)
{
    if (t <= 60) {
        load_tile_async(sb, (t + 3) & 3, kg, vg, (t + 3) << 6, tid);
        CP_COMMIT();
    }
    const uint32_t vb  = sb + SM_RING + (t & 3)*STAGEB + vlane;        // V(t)
    const uint32_t kbn = sb + SM_RING + ((t + 1) & 3)*STAGEB + klane;  // K(t+1)
    const bool do_next = (t < 63);

    if (do_next) {
        #pragma unroll
        for (int j = 0; j < 8; j++)
            #pragma unroll
            for (int c = 0; c < 4; c++) snxt[j][c] = 0.f;
    }

    #pragma unroll
    for (int ks = 0; ks < 4; ks++) {
        // ---- S(t+1) chunk (tensor pipe; independent of softmax below) ----
        if (do_next) {
            uint32_t qf[4];
            LDSM4(qf, qbase + ks*32);
            uint32_t kf0[4], kf1[4], kf2[4], kf3[4];
            LDSM4(kf0, kbn + 0*(16*PITCH) + ks*32);
            LDSM4(kf1, kbn + 1*(16*PITCH) + ks*32);
            LDSM4(kf2, kbn + 2*(16*PITCH) + ks*32);
            LDSM4(kf3, kbn + 3*(16*PITCH) + ks*32);
            MMA16816(snxt[0], qf, kf0[0], kf0[1]);
            MMA16816(snxt[1], qf, kf0[2], kf0[3]);
            MMA16816(snxt[2], qf, kf1[0], kf1[1]);
            MMA16816(snxt[3], qf, kf1[2], kf1[3]);
            MMA16816(snxt[4], qf, kf2[0], kf2[1]);
            MMA16816(snxt[5], qf, kf2[2], kf2[3]);
            MMA16816(snxt[6], qf, kf3[0], kf3[1]);
            MMA16816(snxt[7], qf, kf3[2], kf3[3]);
        }

        // ---- softmax chunk on scur (MUFU pipe) ----
        float* s0 = scur[2*ks];
        float* s1 = scur[2*ks + 1];
        s0[0] = fexp2(s0[0]); s0[1] = fexp2(s0[1]);
        s0[2] = fexp2(s0[2]); s0[3] = fexp2(s0[3]);
        s1[0] = fexp2(s1[0]); s1[1] = fexp2(s1[1]);
        s1[2] = fexp2(s1[2]); s1[3] = fexp2(s1[3]);
        l0 += s0[0] + s0[1] + s1[0] + s1[1];
        l1 += s0[2] + s0[3] + s1[2] + s1[3];

        uint32_t ph[4];
        __half2 h0 = __floats2half2_rn(s0[0], s0[1]);
        __half2 h1 = __floats2half2_rn(s0[2], s0[3]);
        __half2 h2 = __floats2half2_rn(s1[0], s1[1]);
        __half2 h3 = __floats2half2_rn(s1[2], s1[3]);
        ph[0] = *reinterpret_cast<uint32_t*>(&h0);
        ph[1] = *reinterpret_cast<uint32_t*>(&h1);
        ph[2] = *reinterpret_cast<uint32_t*>(&h2);
        ph[3] = *reinterpret_cast<uint32_t*>(&h3);

        // ---- O(t) chunk ----
        #pragma unroll
        for (int cg = 0; cg < 4; cg++) {
            uint32_t vf[4];
            LDSM4T(vf, vb + ks*(16*PITCH) + cg*32);
            MMA16816(oacc[2*cg],   ph, vf[0], vf[1]);
            MMA16816(oacc[2*cg+1], ph, vf[2], vf[3]);
        }
    }

    if (t >= 61) CP_WAIT0(); else CP_WAIT1();
    __syncthreads();
}

__global__ __launch_bounds__(256, 2) void attn_kernel(
    const float* __restrict__ wm, const float* __restrict__ bm,
    float* __restrict__ out)
{
    extern __shared__ __align__(16) char smem[];
    const uint32_t sb = smem_u32(smem);

    int tid = threadIdx.x, wid = tid >> 5, lane = tid & 31;
    int b  = blockIdx.x >> 5;
    int it = blockIdx.x & 31;
    int n0 = it << 7;

    const __half* kg = g_k + (size_t)b*HW_*C_;
    const __half* vg = g_v + (size_t)b*HW_*C_;

    // ---- stage Q (persistent region [0, 18432)) ----
    {
        const float4* q4 = (const float4*)(g_q + ((size_t)b*HW_ + n0)*C_);
        #pragma unroll
        for (int k = 0; k < 4; k++) {
            int e = tid + 256*k;
            *(float4*)(smem + (e >> 3)*PITCH + (e & 7)*16) = q4[e];
        }
    }

    // ---- prologue: issue tiles 0,1,2; wait-leaving-1 -> 0,1 visible ----
    load_tile_async(sb, 0, kg, vg, 0,   tid); CP_COMMIT();
    load_tile_async(sb, 1, kg, vg, 64,  tid); CP_COMMIT();
    load_tile_async(sb, 2, kg, vg, 128, tid); CP_COMMIT();
    CP_WAIT1();
    __syncthreads();

    const uint32_t qbase = sb + (16*wid + (lane & 15))*PITCH + ((lane >> 4) & 1)*16;
    const uint32_t klane = ((lane & 7) + ((lane >> 4) & 1)*8)*PITCH + ((lane >> 3) & 1)*16;
    const uint32_t vlane = 9216 + ((lane & 7) + ((lane >> 3) & 1)*8)*PITCH + ((lane >> 4) & 1)*16;

    float oacc[8][4], sA[8][4], sB[8][4];
    #pragma unroll
    for (int j = 0; j < 8; j++)
        #pragma unroll
        for (int c = 0; c < 4; c++) { oacc[j][c] = 0.f; sA[j][c] = 0.f; }
    float l0 = 0.f, l1 = 0.f;

    // ---- precompute S(0) into sA ----
    {
        const uint32_t kb0 = sb + SM_RING + klane;
        #pragma unroll
        for (int ks = 0; ks < 4; ks++) {
            uint32_t qf[4];
            LDSM4(qf, qbase + ks*32);
            uint32_t kf0[4], kf1[4], kf2[4], kf3[4];
            LDSM4(kf0, kb0 + 0*(16*PITCH) + ks*32);
            LDSM4(kf1, kb0 + 1*(16*PITCH) + ks*32);
            LDSM4(kf2, kb0 + 2*(16*PITCH) + ks*32);
            LDSM4(kf3, kb0 + 3*(16*PITCH) + ks*32);
            MMA16816(sA[0], qf, kf0[0], kf0[1]);
            MMA16816(sA[1], qf, kf0[2], kf0[3]);
            MMA16816(sA[2], qf, kf1[0], kf1[1]);
            MMA16816(sA[3], qf, kf1[2], kf1[3]);
            MMA16816(sA[4], qf, kf2[0], kf2[1]);
            MMA16816(sA[5], qf, kf2[2], kf2[3]);
            MMA16816(sA[6], qf, kf3[0], kf3[1]);
            MMA16816(sA[7], qf, kf3[2], kf3[3]);
        }
    }

    // ---- pipelined main loop (64 iters, unrolled x2 for sacc ping-pong) ----
    for (int tt = 0; tt < 32; tt++) {
        attn_iter(2*tt,     sb, kg, vg, tid, qbase, klane, vlane, sA, sB, oacc, l0, l1);
        attn_iter(2*tt + 1, sb, kg, vg, tid, qbase, klane, vlane, sB, sA, oacc, l0, l1);
    }

    // ---- epilogue ----
    l0 += __shfl_xor_sync(0xffffffffu, l0, 1);
    l0 += __shfl_xor_sync(0xffffffffu, l0, 2);
    l1 += __shfl_xor_sync(0xffffffffu, l1, 1);
    l1 += __shfl_xor_sync(0xffffffffu, l1, 2);
    float inv0 = 1.f / l0, inv1 = 1.f / l1;

    float* sm_o = (float*)smem;               // o^T [64 c][132] = 33792 B
    float* wmT  = (float*)(smem + 36864);     // wmT[c][d] 16384 B
    {
        int r  = 16*wid + (lane >> 2);
        int c0 = 2*(lane & 3);
        #pragma unroll
        for (int j = 0; j < 8; j++) {
            sm_o[(8*j + c0    )*132 + r]     = oacc[j][0]*inv0;
            sm_o[(8*j + c0 + 1)*132 + r]     = oacc[j][1]*inv0;
            sm_o[(8*j + c0    )*132 + r + 8] = oacc[j][2]*inv1;
            sm_o[(8*j + c0 + 1)*132 + r + 8] = oacc[j][3]*inv1;
        }
    }
    #pragma unroll
    for (int k = 0; k < 16; k++) {
        int e = tid + 256*k;
        wmT[(e & 63)*64 + (e >> 6)] = wm[e];
    }
    __syncthreads();

    int tx = tid & 15, ty = tid >> 4;
    float4 bmv = ((const float4*)bm)[tx];
    float acc[8][4];
    #pragma unroll
    for (int ii = 0; ii < 8; ii++) {
        acc[ii][0] = bmv.x; acc[ii][1] = bmv.y; acc[ii][2] = bmv.z; acc[ii][3] = bmv.w;
    }
    #pragma unroll 8
    for (int c = 0; c < 64; c++) {
        float4 wv = *(const float4*)(wmT + c*64 + 4*tx);
        float4 o0 = *(const float4*)(sm_o + c*132 + 8*ty);
        float4 o1 = *(const float4*)(sm_o + c*132 + 8*ty + 4);
        float ov[8] = {o0.x,o0.y,o0.z,o0.w,o1.x,o1.y,o1.z,o1.w};
        #pragma unroll
        for (int ii = 0; ii < 8; ii++) {
            acc[ii][0] = fmaf(ov[ii], wv.x, acc[ii][0]);
            acc[ii][1] = fmaf(ov[ii], wv.y, acc[ii][1]);
            acc[ii][2] = fmaf(ov[ii], wv.z, acc[ii][2]);
            acc[ii][3] = fmaf(ov[ii], wv.w, acc[ii][3]);
        }
    }
    __syncthreads();

    float* sm_mx = (float*)smem;    // mixed [128 t][68]
    #pragma unroll
    for (int ii = 0; ii < 8; ii++) {
        float4 mv = make_float4(fmaxf(acc[ii][0], 0.f), fmaxf(acc[ii][1], 0.f),
                                fmaxf(acc[ii][2], 0.f), fmaxf(acc[ii][3], 0.f));
        *(float4*)(sm_mx + (8*ty + ii)*68 + 4*tx) = mv;
    }
    __syncthreads();

    float* ob = out + (size_t)b*C_*1024 + (size_t)it*32;
    #pragma unroll
    for (int k = 0; k < 8; k++) {
        int e = tid + 256*k;
        int j = e & 31, d = e >> 5;
        float v = sm_mx[(2*j)*68 + d] + sm_mx[(2*j + 1)*68 + d]
                + sm_mx[(64 + 2*j)*68 + d] + sm_mx[(64 + 2*j + 1)*68 + d];
        ob[(size_t)d*1024 + j] = 0.25f * v;
    }
}

extern "C" void kernel_launch(void* const* d_in, const int* in_sizes, int n_in,
                              void* d_out, int out_size)
{
    const float* x  = (const float*)d_in[0];
    const float* wq = (const float*)d_in[1];
    const float* bq = (const float*)d_in[2];
    const float* wk = (const float*)d_in[3];
    const float* bk = (const float*)d_in[4];
    const float* wv = (const float*)d_in[5];
    const float* bv = (const float*)d_in[6];
    const float* wm = (const float*)d_in[7];
    const float* bm = (const float*)d_in[8];
    float* out = (float*)d_out;

    cudaFuncSetAttribute(attn_kernel, cudaFuncAttributeMaxDynamicSharedMemorySize, ATTN_SMEM);

    qkv_kernel<<<256, 256>>>(x, wq, bq, wk, bk, wv, bv);
    attn_kernel<<<256, 256, ATTN_SMEM>>>(wm, bm, out);
}

// round 16
// speedup vs baseline: 1.1303x; 1.1303x over previous
#include <cuda_runtime.h>
#include <cuda_fp16.h>
#include <cstdint>

#define B_  8
#define C_  64
#define HW_ 4096

// ---------------- scratch globals (no allocation) ----------------
__device__ __half g_q[(size_t)B_*HW_*C_];   // [b][n][c]  (scaled by log2e/8)
__device__ __half g_k[(size_t)B_*HW_*C_];   // [b][n][c]
__device__ __half g_v[(size_t)B_*HW_*C_];   // [b][n][c]

__device__ __forceinline__ uint32_t smem_u32(const void* p) {
    uint32_t a;
    asm("{ .reg .u64 t; cvta.to.shared.u64 t, %1; cvt.u32.u64 %0, t; }" : "=r"(a) : "l"(p));
    return a;
}

#define MMA16816(c, a, b0, b1)                                                  \
    asm volatile("mma.sync.aligned.m16n8k16.row.col.f32.f16.f16.f32 "           \
        "{%0,%1,%2,%3}, {%4,%5,%6,%7}, {%8,%9}, {%0,%1,%2,%3};"                 \
        : "+f"((c)[0]), "+f"((c)[1]), "+f"((c)[2]), "+f"((c)[3])                \
        : "r"((a)[0]), "r"((a)[1]), "r"((a)[2]), "r"((a)[3]), "r"(b0), "r"(b1))

#define LDSM4(r, a)                                                             \
    asm volatile("ldmatrix.sync.aligned.m8n8.x4.shared.b16 {%0,%1,%2,%3}, [%4];"\
        : "=r"((r)[0]), "=r"((r)[1]), "=r"((r)[2]), "=r"((r)[3]) : "r"(a))

#define LDSM4T(r, a)                                                            \
    asm volatile("ldmatrix.sync.aligned.m8n8.x4.trans.shared.b16 {%0,%1,%2,%3}, [%4];"\
        : "=r"((r)[0]), "=r"((r)[1]), "=r"((r)[2]), "=r"((r)[3]) : "r"(a))

// hardware exp2 (MUFU.EX2 f32)
__device__ __forceinline__ float fexp2(float x) {
    float y;
    asm("ex2.approx.f32 %0, %1;" : "=f"(y) : "f"(x));
    return y;
}

#define PITCH 144   // bytes per 64-half row (8 halves padding)

// ---------------------------------------------------------------------------
// QKV projection via HMMA (R15 version — conflict-free xs staging, ~6us).
// ---------------------------------------------------------------------------
__global__ __launch_bounds__(256) void qkv_kernel(
    const float* __restrict__ x,
    const float* __restrict__ wq, const float* __restrict__ bq,
    const float* __restrict__ wk, const float* __restrict__ bk,
    const float* __restrict__ wv, const float* __restrict__ bv)
{
    __shared__ __align__(16) char xs[128*PITCH];
    __shared__ __align__(16) char ws[3*64*PITCH];
    __shared__ float bsh[3*64];

    int tid = threadIdx.x, wid = tid >> 5, lane = tid & 31;
    int b  = blockIdx.x >> 5;
    int n0 = (blockIdx.x & 31) << 7;
    const float* xb = x + (size_t)b*C_*HW_;

    // x tile: thread gathers 8 channels of one token (reads coalesced across
    // lanes), packs to 8 halves, one 16B store (conflict-free)
    #pragma unroll
    for (int k = 0; k < 4; k++) {
        int e = tid + 256*k;              // 1024 tasks: 128 rows x 8 chunks
        int row = e & 127;
        int ch  = (e >> 7) & 7;
        const float* src = xb + (size_t)(ch*8)*HW_ + n0 + row;
        __half h[8];
        #pragma unroll
        for (int i = 0; i < 8; i++) h[i] = __float2half_rn(src[(size_t)i*HW_]);
        *(uint4*)(xs + row*PITCH + ch*16) = *(uint4*)h;
    }
    const float* wptr[3] = {wq, wk, wv};
    #pragma unroll
    for (int m = 0; m < 3; m++) {
        char* wsm = ws + m*64*PITCH;
        #pragma unroll
        for (int k = 0; k < 4; k++) {
            int e = tid + 256*k;
            int d = e >> 4, c4 = (e & 15) << 2;
            float4 v = *(const float4*)(wptr[m] + (size_t)d*C_ + c4);
            __half2 h01 = __floats2half2_rn(v.x, v.y);
            __half2 h23 = __floats2half2_rn(v.z, v.w);
            *(__half2*)(wsm + d*PITCH + c4*2)     = h01;
            *(__half2*)(wsm + d*PITCH + c4*2 + 4) = h23;
        }
    }
    if (tid < 192) {
        bsh[tid] = (tid < 64) ? bq[tid] : (tid < 128) ? bk[tid - 64] : bv[tid - 128];
    }
    __syncthreads();

    const uint32_t sxs = smem_u32(xs);
    const uint32_t sws = smem_u32(ws);

    uint32_t af[4][4];
    {
        int r  = 16*wid + (lane & 15);
        int cg = (lane >> 4) & 1;
        #pragma unroll
        for (int ks = 0; ks < 4; ks++)
            LDSM4(af[ks], sxs + r*PITCH + (ks*16 + cg*8)*2);
    }

    const uint32_t blane = ((lane & 7) + ((lane >> 4) & 1)*8)*PITCH + ((lane >> 3) & 1)*16;
    __half* outp[3] = {g_q + (size_t)b*HW_*C_, g_k + (size_t)b*HW_*C_, g_v + (size_t)b*HW_*C_};
    const float scl[3] = {0.18033688011112043f, 1.0f, 1.0f};   // log2(e)/8 on Q

    int r = lane >> 2, c0 = 2*(lane & 3);
    #pragma unroll
    for (int m = 0; m < 3; m++) {
        float acc[8][4];
        #pragma unroll
        for (int j = 0; j < 8; j++)
            #pragma unroll
            for (int c = 0; c < 4; c++) acc[j][c] = 0.f;

        const uint32_t wb = sws + m*64*PITCH + blane;
        #pragma unroll
        for (int ks = 0; ks < 4; ks++) {
            uint32_t f0[4], f1[4], f2[4], f3[4];
            LDSM4(f0, wb + 0*(16*PITCH) + ks*32);
            LDSM4(f1, wb + 1*(16*PITCH) + ks*32);
            LDSM4(f2, wb + 2*(16*PITCH) + ks*32);
            LDSM4(f3, wb + 3*(16*PITCH) + ks*32);
            MMA16816(acc[0], af[ks], f0[0], f0[1]);
            MMA16816(acc[1], af[ks], f0[2], f0[3]);
            MMA16816(acc[2], af[ks], f1[0], f1[1]);
            MMA16816(acc[3], af[ks], f1[2], f1[3]);
            MMA16816(acc[4], af[ks], f2[0], f2[1]);
            MMA16816(acc[5], af[ks], f2[2], f2[3]);
            MMA16816(acc[6], af[ks], f3[0], f3[1]);
            MMA16816(acc[7], af[ks], f3[2], f3[3]);
        }

        float sc = scl[m];
        __half* og = outp[m] + (size_t)(n0 + 16*wid + r)*C_;
        #pragma unroll
        for (int j = 0; j < 8; j++) {
            float bz0 = bsh[m*64 + 8*j + c0], bz1 = bsh[m*64 + 8*j + c0 + 1];
            __half2 lo = __floats2half2_rn((acc[j][0] + bz0)*sc, (acc[j][1] + bz1)*sc);
            __half2 hi = __floats2half2_rn((acc[j][2] + bz0)*sc, (acc[j][3] + bz1)*sc);
            *(__half2*)(og + 8*j + c0)        = lo;
            *(__half2*)(og + 8*C_ + 8*j + c0) = hi;
        }
    }
}

// ---------------------------------------------------------------------------
// Fused flash attention (R6/R13 exactly — best measured 119.4us): HMMA,
// register-staged double-buffered K/V, interleaved f32 MUFU softmax,
// mix/ReLU/2x2-pool epilogue. One CTA per (b, 128-query tile).
// ---------------------------------------------------------------------------
#define KVBUF 18432
#define SM_WMT 36864
#define ATTN_SMEM (36864 + 16384)

__global__ __launch_bounds__(256, 2) void attn_kernel(
    const float* __restrict__ wm, const float* __restrict__ bm,
    float* __restrict__ out)
{
    extern __shared__ __align__(16) char smem[];
    const uint32_t sb = smem_u32(smem);
    float* wmT = (float*)(smem + SM_WMT);

    int tid = threadIdx.x, wid = tid >> 5, lane = tid & 31;
    int b  = blockIdx.x >> 5;
    int it = blockIdx.x & 31;
    int n0 = it << 7;

    const __half* kg = g_k + (size_t)b*HW_*C_;
    const __half* vg = g_v + (size_t)b*HW_*C_;

    #pragma unroll
    for (int k = 0; k < 16; k++) {
        int e = tid + 256*k;
        wmT[(e & 63)*64 + (e >> 6)] = wm[e];
    }

    const int e0 = tid, e1 = tid + 256;
    const int so0 = (e0 >> 3)*PITCH + (e0 & 7)*16;
    const int so1 = (e1 >> 3)*PITCH + (e1 & 7)*16;

    {
        const float4* q4 = (const float4*)(g_q + ((size_t)b*HW_ + n0)*C_);
        #pragma unroll
        for (int k = 0; k < 4; k++) {
            int e = tid + 256*k;
            *(float4*)(smem + (e >> 3)*PITCH + (e & 7)*16) = q4[e];
        }
    }
    __syncthreads();

    uint32_t qf[4][4];
    {
        int r  = 16*wid + (lane & 15);
        int cg = (lane >> 4) & 1;
        #pragma unroll
        for (int kt = 0; kt < 4; kt++)
            LDSM4(qf[kt], sb + r*PITCH + (kt*16 + cg*8)*2);
    }

    float4 rk0, rk1, rv0, rv1;
    {
        const float4* k4 = (const float4*)kg;
        const float4* v4 = (const float4*)vg;
        rk0 = k4[e0]; rk1 = k4[e1]; rv0 = v4[e0]; rv1 = v4[e1];
    }
    __syncthreads();
    *(float4*)(smem + so0) = rk0;        *(float4*)(smem + so1) = rk1;
    *(float4*)(smem + 9216 + so0) = rv0; *(float4*)(smem + 9216 + so1) = rv1;
    {
        const float4* k4 = (const float4*)(kg + (size_t)64*C_);
        const float4* v4 = (const float4*)(vg + (size_t)64*C_);
        rk0 = k4[e0]; rk1 = k4[e1]; rv0 = v4[e0]; rv1 = v4[e1];
    }

    float oacc[8][4];
    #pragma unroll
    for (int j = 0; j < 8; j++)
        #pragma unroll
        for (int c = 0; c < 4; c++) oacc[j][c] = 0.f;
    float l0 = 0.f, l1 = 0.f;

    const uint32_t klane = ((lane & 7) + ((lane >> 4) & 1)*8)*PITCH + ((lane >> 3) & 1)*16;
    const uint32_t vlane = 9216 + ((lane & 7) + ((lane >> 3) & 1)*8)*PITCH + ((lane >> 4) & 1)*16;

    for (int t = 0; t < 64; t++) {
        __syncthreads();
        uint32_t cur = sb + (t & 1)*KVBUF;

        if (t < 63) {
            char* nb = smem + ((t + 1) & 1)*KVBUF;
            *(float4*)(nb + so0) = rk0;        *(float4*)(nb + so1) = rk1;
            *(float4*)(nb + 9216 + so0) = rv0; *(float4*)(nb + 9216 + so1) = rv1;
            if (t < 62) {
                const float4* k4 = (const float4*)(kg + (size_t)(t + 2)*64*C_);
                const float4* v4 = (const float4*)(vg + (size_t)(t + 2)*64*C_);
                rk0 = k4[e0]; rk1 = k4[e1]; rv0 = v4[e0]; rv1 = v4[e1];
            }
        }

        float sacc[8][4];
        #pragma unroll
        for (int j = 0; j < 8; j++)
            #pragma unroll
            for (int c = 0; c < 4; c++) sacc[j][c] = 0.f;

        const uint32_t kb = cur + klane;
        #pragma unroll
        for (int ks = 0; ks < 4; ks++) {
            uint32_t kf0[4], kf1[4], kf2[4], kf3[4];
            LDSM4(kf0, kb + 0*(16*PITCH) + ks*32);
            LDSM4(kf1, kb + 1*(16*PITCH) + ks*32);
            LDSM4(kf2, kb + 2*(16*PITCH) + ks*32);
            LDSM4(kf3, kb + 3*(16*PITCH) + ks*32);
            MMA16816(sacc[0], qf[ks], kf0[0], kf0[1]);
            MMA16816(sacc[1], qf[ks], kf0[2], kf0[3]);
            MMA16816(sacc[2], qf[ks], kf1[0], kf1[1]);
            MMA16816(sacc[3], qf[ks], kf1[2], kf1[3]);
            MMA16816(sacc[4], qf[ks], kf2[0], kf2[1]);
            MMA16816(sacc[5], qf[ks], kf2[2], kf2[3]);
            MMA16816(sacc[6], qf[ks], kf3[0], kf3[1]);
            MMA16816(sacc[7], qf[ks], kf3[2], kf3[3]);
        }

        const uint32_t vb = cur + vlane;
        #pragma unroll
        for (int ks = 0; ks < 4; ks++) {
            float* s0 = sacc[2*ks];
            float* s1 = sacc[2*ks + 1];
            s0[0] = fexp2(s0[0]); s0[1] = fexp2(s0[1]);
            s0[2] = fexp2(s0[2]); s0[3] = fexp2(s0[3]);
            s1[0] = fexp2(s1[0]); s1[1] = fexp2(s1[1]);
            s1[2] = fexp2(s1[2]); s1[3] = fexp2(s1[3]);
            l0 += s0[0] + s0[1] + s1[0] + s1[1];
            l1 += s0[2] + s0[3] + s1[2] + s1[3];

            uint32_t ph[4];
            __half2 h0 = __floats2half2_rn(s0[0], s0[1]);
            __half2 h1 = __floats2half2_rn(s0[2], s0[3]);
            __half2 h2 = __floats2half2_rn(s1[0], s1[1]);
            __half2 h3 = __floats2half2_rn(s1[2], s1[3]);
            ph[0] = *reinterpret_cast<uint32_t*>(&h0);
            ph[1] = *reinterpret_cast<uint32_t*>(&h1);
            ph[2] = *reinterpret_cast<uint32_t*>(&h2);
            ph[3] = *reinterpret_cast<uint32_t*>(&h3);

            #pragma unroll
            for (int cg = 0; cg < 4; cg++) {
                uint32_t vf[4];
                LDSM4T(vf, vb + ks*(16*PITCH) + cg*32);
                MMA16816(oacc[2*cg],   ph, vf[0], vf[1]);
                MMA16816(oacc[2*cg+1], ph, vf[2], vf[3]);
            }
        }
    }

    // ---- epilogue: normalize, mix GEMM + ReLU, 2x2 pool, store ----
    l0 += __shfl_xor_sync(0xffffffffu, l0, 1);
    l0 += __shfl_xor_sync(0xffffffffu, l0, 2);
    l1 += __shfl_xor_sync(0xffffffffu, l1, 1);
    l1 += __shfl_xor_sync(0xffffffffu, l1, 2);
    float inv0 = 1.f / l0, inv1 = 1.f / l1;

    __syncthreads();
    float* sm_o = (float*)smem;     // o^T [64 c][132]
    {
        int r  = 16*wid + (lane >> 2);
        int c0 = 2*(lane & 3);
        #pragma unroll
        for (int j = 0; j < 8; j++) {
            sm_o[(8*j + c0    )*132 + r]     = oacc[j][0]*inv0;
            sm_o[(8*j + c0 + 1)*132 + r]     = oacc[j][1]*inv0;
            sm_o[(8*j + c0    )*132 + r + 8] = oacc[j][2]*inv1;
            sm_o[(8*j + c0 + 1)*132 + r + 8] = oacc[j][3]*inv1;
        }
    }
    __syncthreads();

    int tx = tid & 15, ty = tid >> 4;
    float4 bmv = ((const float4*)bm)[tx];
    float acc[8][4];
    #pragma unroll
    for (int ii = 0; ii < 8; ii++) {
        acc[ii][0] = bmv.x; acc[ii][1] = bmv.y; acc[ii][2] = bmv.z; acc[ii][3] = bmv.w;
    }
    #pragma unroll 8
    for (int c = 0; c < 64; c++) {
        float4 wv = *(const float4*)(wmT + c*64 + 4*tx);
        float4 o0 = *(const float4*)(sm_o + c*132 + 8*ty);
        float4 o1 = *(const float4*)(sm_o + c*132 + 8*ty + 4);
        float ov[8] = {o0.x,o0.y,o0.z,o0.w,o1.x,o1.y,o1.z,o1.w};
        #pragma unroll
        for (int ii = 0; ii < 8; ii++) {
            acc[ii][0] = fmaf(ov[ii], wv.x, acc[ii][0]);
            acc[ii][1] = fmaf(ov[ii], wv.y, acc[ii][1]);
            acc[ii][2] = fmaf(ov[ii], wv.z, acc[ii][2]);
            acc[ii][3] = fmaf(ov[ii], wv.w, acc[ii][3]);
        }
    }
    __syncthreads();

    float* sm_mx = (float*)smem;    // mixed [128 t][68]
    #pragma unroll
    for (int ii = 0; ii < 8; ii++) {
        float4 mv = make_float4(fmaxf(acc[ii][0], 0.f), fmaxf(acc[ii][1], 0.f),
                                fmaxf(acc[ii][2], 0.f), fmaxf(acc[ii][3], 0.f));
        *(float4*)(sm_mx + (8*ty + ii)*68 + 4*tx) = mv;
    }
    __syncthreads();

    float* ob = out + (size_t)b*C_*1024 + (size_t)it*32;
    #pragma unroll
    for (int k = 0; k < 8; k++) {
        int e = tid + 256*k;
        int j = e & 31, d = e >> 5;
        float v = sm_mx[(2*j)*68 + d] + sm_mx[(2*j + 1)*68 + d]
                + sm_mx[(64 + 2*j)*68 + d] + sm_mx[(64 + 2*j + 1)*68 + d];
        ob[(size_t)d*1024 + j] = 0.25f * v;
    }
}

extern "C" void kernel_launch(void* const* d_in, const int* in_sizes, int n_in,
                              void* d_out, int out_size)
{
    const float* x  = (const float*)d_in[0];
    const float* wq = (const float*)d_in[1];
    const float* bq = (const float*)d_in[2];
    const float* wk = (const float*)d_in[3];
    const float* bk = (const float*)d_in[4];
    const float* wv = (const float*)d_in[5];
    const float* bv = (const float*)d_in[6];
    const float* wm = (const float*)d_in[7];
    const float* bm = (const float*)d_in[8];
    float* out = (float*)d_out;

    cudaFuncSetAttribute(attn_kernel, cudaFuncAttributeMaxDynamicSharedMemorySize, ATTN_SMEM);

    qkv_kernel<<<256, 256>>>(x, wq, bq, wk, bk, wv, bv);
    attn_kernel<<<256, 256, ATTN_SMEM>>>(wm, bm, out);
}